// round 7
// baseline (speedup 1.0000x reference)
#include <cuda_runtime.h>
#include <cuda_bf16.h>
#include <cstdint>

#define SLEN 1024
#define BATCH 256
#define DIN 64
#define HID 128
#define KROW2 136          // padded halves per B row (68 words)

// xp (phase 1) then h (phase 2), layout [dir][b][t][j]
__device__ float g_buf[2u * BATCH * SLEN * HID];

typedef unsigned int u32;

static __device__ __forceinline__ u32 bfpack(float a0, float a1) {
    u32 r; asm("cvt.rn.bf16x2.f32 %0, %1, %2;" : "=r"(r) : "f"(a1), "f"(a0)); return r;
}
static __device__ __forceinline__ float bfres(float a) {
    return a - __bfloat162float(__float2bfloat16(a));
}
static __device__ __forceinline__ void mma16816(float c[4], const u32 a[4], const u32 b[2]) {
    asm("mma.sync.aligned.m16n8k16.row.col.f32.bf16.bf16.f32 "
        "{%0,%1,%2,%3}, {%4,%5,%6,%7}, {%8,%9}, {%0,%1,%2,%3};"
        : "+f"(c[0]), "+f"(c[1]), "+f"(c[2]), "+f"(c[3])
        : "r"(a[0]), "r"(a[1]), "r"(a[2]), "r"(a[3]), "r"(b[0]), "r"(b[1]));
}
static __device__ __forceinline__ float fast_tanh(float x) {
    float e, r;
    asm("ex2.approx.f32 %0, %1;" : "=f"(e) : "f"(x * 2.8853900817779268f));
    asm("rcp.approx.f32 %0, %1;" : "=f"(r) : "f"(e + 1.0f));
    return fmaf(-2.0f, r, 1.0f);
}

// ===== Phase 1: xp[dir][b][t][j] = x[b,t,:] . Wih[dir][j,:]
// Block: M=64 (t rows, one b) x N=128 (all j), K=64. 256 threads (8 warps, 2M x 4N).
// Dynamic smem: xs_h/xs_l (64x36 words), ws_h/ws_l (128x36 words) = 55296 B.
__global__ __launch_bounds__(256)
void xp_gemm(const float* __restrict__ x,
             const float* __restrict__ Wih_fw, const float* __restrict__ Wih_bw)
{
    extern __shared__ u32 sm[];
    u32* xs_h = sm;                 // 64*36 = 2304
    u32* xs_l = sm + 2304;
    u32* ws_h = sm + 4608;          // 128*36 = 4608
    u32* ws_l = sm + 9216;

    const int tid  = threadIdx.x;
    const int lane = tid & 31;
    const int wid  = tid >> 5;
    const int wm = wid & 1, wn = wid >> 1;
    const int g = lane >> 2, t4 = lane & 3;

    const int T   = blockIdx.x;
    const int b   = T >> 4;
    const int t0  = (T & 15) * 64;
    const int dir = blockIdx.y;

    const float* W    = dir ? Wih_bw : Wih_fw;
    const float* xsrc = x + ((size_t)b * SLEN + t0) * DIN;

    // stage x (64x64): 1024 float4, 4 per thread
    #pragma unroll
    for (int i = 0; i < 4; ++i) {
        const int idx = tid + i * 256;
        const int row = idx >> 4;
        const int w   = row * 36 + ((idx & 15) << 1);
        float4 v = ((const float4*)xsrc)[idx];
        *(uint2*)(xs_h + w) = make_uint2(bfpack(v.x, v.y), bfpack(v.z, v.w));
        *(uint2*)(xs_l + w) = make_uint2(bfpack(bfres(v.x), bfres(v.y)),
                                         bfpack(bfres(v.z), bfres(v.w)));
    }
    // stage W (128x64): 2048 float4, 8 per thread
    #pragma unroll
    for (int i = 0; i < 8; ++i) {
        const int idx = tid + i * 256;
        const int row = idx >> 4;
        const int w   = row * 36 + ((idx & 15) << 1);
        float4 v = ((const float4*)W)[idx];
        *(uint2*)(ws_h + w) = make_uint2(bfpack(v.x, v.y), bfpack(v.z, v.w));
        *(uint2*)(ws_l + w) = make_uint2(bfpack(bfres(v.x), bfres(v.y)),
                                         bfpack(bfres(v.z), bfres(v.w)));
    }
    __syncthreads();

    float acc[2][4][4];
    #pragma unroll
    for (int mt = 0; mt < 2; ++mt)
        #pragma unroll
        for (int nt = 0; nt < 4; ++nt)
            #pragma unroll
            for (int c = 0; c < 4; ++c) acc[mt][nt][c] = 0.0f;

    #pragma unroll
    for (int kc = 0; kc < 4; ++kc) {
        const int base = 8 * kc + t4;
        u32 ah[2][4], al[2][4], bh[4][2], bl[4][2];
        #pragma unroll
        for (int mt = 0; mt < 2; ++mt) {
            const int r = wm * 32 + mt * 16 + g;
            ah[mt][0] = xs_h[r*36 + base];      ah[mt][1] = xs_h[(r+8)*36 + base];
            ah[mt][2] = xs_h[r*36 + base + 4];  ah[mt][3] = xs_h[(r+8)*36 + base + 4];
            al[mt][0] = xs_l[r*36 + base];      al[mt][1] = xs_l[(r+8)*36 + base];
            al[mt][2] = xs_l[r*36 + base + 4];  al[mt][3] = xs_l[(r+8)*36 + base + 4];
        }
        #pragma unroll
        for (int nt = 0; nt < 4; ++nt) {
            const int n = wn * 32 + nt * 8 + g;
            bh[nt][0] = ws_h[n*36 + base];  bh[nt][1] = ws_h[n*36 + base + 4];
            bl[nt][0] = ws_l[n*36 + base];  bl[nt][1] = ws_l[n*36 + base + 4];
        }
        #pragma unroll
        for (int mt = 0; mt < 2; ++mt)
            #pragma unroll
            for (int nt = 0; nt < 4; ++nt) {
                mma16816(acc[mt][nt], ah[mt], bh[nt]);
                mma16816(acc[mt][nt], ah[mt], bl[nt]);
                mma16816(acc[mt][nt], al[mt], bh[nt]);
            }
    }

    // epilogue -> g_buf[dir][b][t][j]
    float* obase = g_buf + ((size_t)(dir * BATCH + b) * SLEN + t0) * HID;
    #pragma unroll
    for (int mt = 0; mt < 2; ++mt) {
        const int r0 = wm * 32 + mt * 16 + g;
        #pragma unroll
        for (int nt = 0; nt < 4; ++nt) {
            const int j = wn * 32 + nt * 8 + 2 * t4;
            *(float2*)(obase + (size_t)r0 * HID + j)       = make_float2(acc[mt][nt][0], acc[mt][nt][1]);
            *(float2*)(obase + (size_t)(r0 + 8) * HID + j) = make_float2(acc[mt][nt][2], acc[mt][nt][3]);
        }
    }
}

// ===== Phase 2: recurrence, K=128. 64 blocks (2 dir x 32 groups of 8), 256 thr (8 warps).
// Per step: D[j(128), b(8)] = Whh . h, bf16 hi/lo 3-product. A register-resident.
__global__ __launch_bounds__(256, 1)
void birnn_recur(const float* __restrict__ Whh_fw, const float* __restrict__ Whh_bw,
                 const float* __restrict__ bih_fw, const float* __restrict__ bhh_fw,
                 const float* __restrict__ bih_bw, const float* __restrict__ bhh_bw)
{
    __shared__ unsigned short hbH[8 * KROW2];   // B hi: [batch 8][j 128 pad 136]
    __shared__ unsigned short hbL[8 * KROW2];   // B lo

    const int tid  = threadIdx.x;
    const int lane = tid & 31;
    const int w    = tid >> 5;
    const int g  = lane >> 2;
    const int t4 = lane & 3;
    const int j0 = 16 * w;
    const int dir = blockIdx.x >> 5;
    const int bb  = (blockIdx.x & 31) * 8;

    const float* Whh = dir ? Whh_bw : Whh_fw;

    // static A fragments: rows j0+g, j0+g+8 over K=128, hi+lo
    u32 ah[8][4], al[8][4];
    #pragma unroll
    for (int kc = 0; kc < 8; ++kc) {
        const int kb = 16 * kc + 2 * t4;
        const float* r0 = Whh + (j0 + g) * HID + kb;
        const float* r1 = Whh + (j0 + g + 8) * HID + kb;
        float2 v0 = *(const float2*)r0;
        float2 v1 = *(const float2*)r1;
        float2 v2 = *(const float2*)(r0 + 8);
        float2 v3 = *(const float2*)(r1 + 8);
        ah[kc][0] = bfpack(v0.x, v0.y);  al[kc][0] = bfpack(bfres(v0.x), bfres(v0.y));
        ah[kc][1] = bfpack(v1.x, v1.y);  al[kc][1] = bfpack(bfres(v1.x), bfres(v1.y));
        ah[kc][2] = bfpack(v2.x, v2.y);  al[kc][2] = bfpack(bfres(v2.x), bfres(v2.y));
        ah[kc][3] = bfpack(v3.x, v3.y);  al[kc][3] = bfpack(bfres(v3.x), bfres(v3.y));
    }

    float bias2[2];
    #pragma unroll
    for (int hh = 0; hh < 2; ++hh) {
        const int j = j0 + g + 8 * hh;
        bias2[hh] = dir ? (bih_bw[j] + bhh_bw[j]) : (bih_fw[j] + bhh_fw[j]);
    }

    // zero B planes (h0 = 0)
    for (int i = tid; i < 8 * (KROW2 / 2); i += 256) ((u32*)hbH)[i] = 0;
    for (int i = tid; i < 8 * (KROW2 / 2); i += 256) ((u32*)hbL)[i] = 0;

    const int t0 = dir ? (SLEN - 1) : 0;
    const int dt = dir ? -1 : 1;

    float* gbase = g_buf + ((size_t)(dir * BATCH + bb) * SLEN + t0) * HID;
    const long gstep = (long)dt * HID;
    int goff[4];
    #pragma unroll
    for (int e = 0; e < 4; ++e)
        goff[e] = (2 * t4 + (e & 1)) * (SLEN * HID) + j0 + g + 8 * (e >> 1);

    // initial xp(t0)
    float xpv[4];
    #pragma unroll
    for (int e = 0; e < 4; ++e) xpv[e] = __ldg(gbase + goff[e]);
    __syncthreads();

    const u32* Hh = (const u32*)hbH;
    const u32* Hl = (const u32*)hbL;

    for (int s = 0; s < SLEN; ++s) {
        // 24 HMMA over K=128, 3 independent accumulator chains
        float a0[4] = {0.f, 0.f, 0.f, 0.f};
        float a1[4] = {0.f, 0.f, 0.f, 0.f};
        float a2[4] = {0.f, 0.f, 0.f, 0.f};
        #pragma unroll
        for (int kc = 0; kc < 8; ++kc) {
            const int w0 = g * 68 + kc * 8 + t4;
            u32 bh[2], bl[2];
            bh[0] = Hh[w0];  bh[1] = Hh[w0 + 4];
            bl[0] = Hl[w0];  bl[1] = Hl[w0 + 4];
            mma16816(a0, ah[kc], bh);
            mma16816(a1, ah[kc], bl);
            mma16816(a2, al[kc], bh);
        }

        // prefetch next xp (hidden under MMA)
        float xpn[4];
        if (s + 1 < SLEN) {
            const float* nb = gbase + gstep;
            #pragma unroll
            for (int e = 0; e < 4; ++e) xpn[e] = __ldg(nb + goff[e]);
        } else {
            #pragma unroll
            for (int e = 0; e < 4; ++e) xpn[e] = 0.f;
        }

        float v[4];
        #pragma unroll
        for (int e = 0; e < 4; ++e)
            v[e] = fast_tanh(a0[e] + a1[e] + a2[e] + xpv[e] + bias2[e >> 1]);

        __syncthreads();   // all B reads for step s complete

        // write B <- h_{s+1} hi/lo, overwrite consumed xp[t] with h[t] in gmem
        #pragma unroll
        for (int e = 0; e < 4; ++e) {
            const int b_ = 2 * t4 + (e & 1);
            const int j_ = j0 + g + 8 * (e >> 1);
            const __nv_bfloat16 hi = __float2bfloat16(v[e]);
            const float hif = __bfloat162float(hi);
            const __nv_bfloat16 lo = __float2bfloat16(v[e] - hif);
            hbH[b_ * KROW2 + j_] = __bfloat16_as_ushort(hi);
            hbL[b_ * KROW2 + j_] = __bfloat16_as_ushort(lo);
            gbase[goff[e]] = v[e];
        }
        gbase += gstep;
        #pragma unroll
        for (int e = 0; e < 4; ++e) xpv[e] = xpn[e];

        __syncthreads();   // B ready for next step
    }
}

// ===== Phase 3: fc head. One warp per (b,t).
__global__ __launch_bounds__(256)
void birnn_fc(const float* __restrict__ fcW, const float* __restrict__ fcb,
              float* __restrict__ out)
{
    const int gw   = (blockIdx.x * blockDim.x + threadIdx.x) >> 5;
    const int lane = threadIdx.x & 31;
    const int b = gw >> 10;
    const int t = gw & 1023;

    const float4* hf = (const float4*)(g_buf + ((size_t)b * SLEN + t) * HID);
    const float4* hb = (const float4*)(g_buf + ((size_t)(BATCH + b) * SLEN + t) * HID);
    float4 a  = hf[lane];
    float4 c  = hb[lane];
    float4 wa = ((const float4*)fcW)[lane];
    float4 wb = ((const float4*)fcW)[32 + lane];

    float s = a.x*wa.x + a.y*wa.y + a.z*wa.z + a.w*wa.w
            + c.x*wb.x + c.y*wb.y + c.z*wb.z + c.w*wb.w;
    #pragma unroll
    for (int m = 16; m > 0; m >>= 1)
        s += __shfl_xor_sync(0xffffffffu, s, m);
    if (lane == 0) out[gw] = s + fcb[0];
}

extern "C" void kernel_launch(void* const* d_in, const int* in_sizes, int n_in,
                              void* d_out, int out_size)
{
    (void)in_sizes; (void)n_in; (void)out_size;
    const float* inputs = (const float*)d_in[0];
    const float* Wih_fw = (const float*)d_in[1];
    const float* Whh_fw = (const float*)d_in[2];
    const float* bih_fw = (const float*)d_in[3];
    const float* bhh_fw = (const float*)d_in[4];
    const float* Wih_bw = (const float*)d_in[5];
    const float* Whh_bw = (const float*)d_in[6];
    const float* bih_bw = (const float*)d_in[7];
    const float* bhh_bw = (const float*)d_in[8];
    const float* fcW    = (const float*)d_in[9];
    const float* fcb    = (const float*)d_in[10];
    float* out = (float*)d_out;

    static const int xp_smem = 55296;
    cudaFuncSetAttribute(xp_gemm, cudaFuncAttributeMaxDynamicSharedMemorySize, xp_smem);

    xp_gemm<<<dim3(BATCH * (SLEN / 64), 2), 256, xp_smem>>>(inputs, Wih_fw, Wih_bw);
    birnn_recur<<<64, 256>>>(Whh_fw, Whh_bw, bih_fw, bhh_fw, bih_bw, bhh_bw);
    birnn_fc<<<(BATCH * SLEN) / 8, 256>>>(fcW, fcb, out);
}

// round 8
// speedup vs baseline: 1.4289x; 1.4289x over previous
#include <cuda_runtime.h>
#include <cuda_bf16.h>
#include <cstdint>

#define SLEN 1024
#define BATCH 256
#define DIN 64
#define HID 128
#define KW 100            // uint2 (hi,lo word pair) per batch row: 96 real + 4 pad

// h outputs for fc pass: [dir][b][t][j]
__device__ float g_h[2u * BATCH * SLEN * HID];

typedef unsigned int u32;

static __device__ __forceinline__ u32 bfpack(float a0, float a1) {
    u32 r; asm("cvt.rn.bf16x2.f32 %0, %1, %2;" : "=r"(r) : "f"(a1), "f"(a0)); return r;
}
static __device__ __forceinline__ float bfres(float a) {
    return a - __bfloat162float(__float2bfloat16(a));
}
static __device__ __forceinline__ void mma16816(float c[4], const u32 a[4], const u32 b[2]) {
    asm("mma.sync.aligned.m16n8k16.row.col.f32.bf16.bf16.f32 "
        "{%0,%1,%2,%3}, {%4,%5,%6,%7}, {%8,%9}, {%0,%1,%2,%3};"
        : "+f"(c[0]), "+f"(c[1]), "+f"(c[2]), "+f"(c[3])
        : "r"(a[0]), "r"(a[1]), "r"(a[2]), "r"(a[3]), "r"(b[0]), "r"(b[1]));
}
static __device__ __forceinline__ float fast_tanh(float x) {
    float e, r;
    asm("ex2.approx.f32 %0, %1;" : "=f"(e) : "f"(x * 2.8853900817779268f));
    asm("rcp.approx.f32 %0, %1;" : "=f"(r) : "f"(e + 1.0f));
    return fmaf(-2.0f, r, 1.0f);
}

// ===== Recurrence: 64 blocks (2 dir x 32 batch-groups of 8), 256 threads (8 warps).
// Per step: D[j(128), b(8)] = [Whh|Wih] . [h|x], K=192, bf16 hi/lo 3-product.
// B tile double-buffered in smem as uint2 = (hi bf16x2, lo bf16x2) per k-pair.
__global__ __launch_bounds__(256, 1)
void birnn_recur(const float* __restrict__ inputs,
                 const float* __restrict__ Whh_fw, const float* __restrict__ Whh_bw,
                 const float* __restrict__ Wih_fw, const float* __restrict__ Wih_bw,
                 const float* __restrict__ bih_fw, const float* __restrict__ bhh_fw,
                 const float* __restrict__ bih_bw, const float* __restrict__ bhh_bw)
{
    __shared__ uint2 C[2][8 * KW];      // [buf][batch 8][k-pair 96 + pad 4]

    const int tid  = threadIdx.x;
    const int lane = tid & 31;
    const int w    = tid >> 5;
    const int g  = lane >> 2;      // 0..7  (n index in B frag / j row in A frag)
    const int t4 = lane & 3;       // 0..3  (k-pair in frags)
    const int j0 = 16 * w;
    const int g100 = g * KW;
    const int dir = blockIdx.x >> 5;
    const int bb  = (blockIdx.x & 31) * 8;

    const float* Whh = dir ? Whh_bw : Whh_fw;
    const float* Wih = dir ? Wih_bw : Wih_fw;

    // ---- static A fragments: rows j0+g, j0+g+8 over K=192, hi+lo ----
    u32 ah[12][4], al[12][4];
    #pragma unroll
    for (int kc = 0; kc < 12; ++kc) {
        const int kb = 16 * kc + 2 * t4;
        const float* r0 = (kc < 8) ? (Whh + (j0 + g) * HID + kb)
                                   : (Wih + (j0 + g) * DIN + (kb - HID));
        const float* r1 = (kc < 8) ? (Whh + (j0 + g + 8) * HID + kb)
                                   : (Wih + (j0 + g + 8) * DIN + (kb - HID));
        float2 v0 = *(const float2*)r0;
        float2 v1 = *(const float2*)r1;
        float2 v2 = *(const float2*)(r0 + 8);
        float2 v3 = *(const float2*)(r1 + 8);
        ah[kc][0] = bfpack(v0.x, v0.y);  al[kc][0] = bfpack(bfres(v0.x), bfres(v0.y));
        ah[kc][1] = bfpack(v1.x, v1.y);  al[kc][1] = bfpack(bfres(v1.x), bfres(v1.y));
        ah[kc][2] = bfpack(v2.x, v2.y);  al[kc][2] = bfpack(bfres(v2.x), bfres(v2.y));
        ah[kc][3] = bfpack(v3.x, v3.y);  al[kc][3] = bfpack(bfres(v3.x), bfres(v3.y));
    }

    float bias2[2];
    #pragma unroll
    for (int hh = 0; hh < 2; ++hh) {
        const int j = j0 + g + 8 * hh;
        bias2[hh] = dir ? (bih_bw[j] + bhh_bw[j]) : (bih_fw[j] + bhh_fw[j]);
    }

    // ---- zero both buffers (h0 = 0, pads 0) ----
    for (int i = tid; i < 2 * 8 * KW; i += 256)
        ((uint2*)C)[i] = make_uint2(0u, 0u);

    // ---- x loader: warp w <-> batch row w; lane covers k-dims 2*lane..2*lane+1 ----
    const int t0 = dir ? (SLEN - 1) : 0;
    const int dt = dir ? -1 : 1;
    const int xb = w;
    const float* xptr = inputs + ((size_t)(bb + xb) * SLEN + t0) * DIN + lane * 2;
    const int xw = xb * KW + 64 + lane;       // uint2 index of this thread's x k-pair

    __syncthreads();
    {
        float2 v = *(const float2*)xptr;
        C[0][xw] = make_uint2(bfpack(v.x, v.y), bfpack(bfres(v.x), bfres(v.y)));
    }

    // ---- gmem h stream ----
    float* gbase = g_h + ((size_t)(dir * BATCH + bb) * SLEN + t0) * HID;
    const long gstep = (long)dt * HID;
    int goff[4];
    #pragma unroll
    for (int e = 0; e < 4; ++e)
        goff[e] = (2 * t4 + (e & 1)) * (SLEN * HID) + j0 + g + 8 * (e >> 1);

    __syncthreads();

    for (int s = 0; s < SLEN; ++s) {
        const uint2* Rd = C[s & 1];

        // prefetch next x (hidden under frag-load + MMA)
        float2 xn = make_float2(0.f, 0.f);
        if (s + 1 < SLEN) {
            xptr += dt * DIN;
            xn = *(const float2*)xptr;
        }

        // ---- preload all B fragments (LDS.64, hi+lo together) ----
        u32 bh[12][2], bl[12][2];
        #pragma unroll
        for (int kc = 0; kc < 12; ++kc) {
            uint2 v0 = Rd[g100 + kc * 8 + t4];
            uint2 v1 = Rd[g100 + kc * 8 + t4 + 4];
            bh[kc][0] = v0.x;  bl[kc][0] = v0.y;
            bh[kc][1] = v1.x;  bl[kc][1] = v1.y;
        }

        // ---- 36 HMMA, 3 independent accumulator chains ----
        float a0[4] = {0.f, 0.f, 0.f, 0.f};
        float a1[4] = {0.f, 0.f, 0.f, 0.f};
        float a2[4] = {0.f, 0.f, 0.f, 0.f};
        #pragma unroll
        for (int kc = 0; kc < 12; ++kc) {
            mma16816(a0, ah[kc], bh[kc]);
            mma16816(a1, ah[kc], bl[kc]);
            mma16816(a2, al[kc], bh[kc]);
        }

        // ---- activate ----
        float v[4];
        #pragma unroll
        for (int e = 0; e < 4; ++e)
            v[e] = fast_tanh(a0[e] + a1[e] + a2[e] + bias2[e >> 1]);

        // ---- write h_{s+1} hi/lo into the OTHER buffer + stream to gmem ----
        unsigned short* Wu = (unsigned short*)C[(s + 1) & 1];
        #pragma unroll
        for (int e = 0; e < 4; ++e) {
            const int b_ = 2 * t4 + (e & 1);
            const int j_ = j0 + g + 8 * (e >> 1);
            const __nv_bfloat16 hi = __float2bfloat16(v[e]);
            const float hif = __bfloat162float(hi);
            const __nv_bfloat16 lo = __float2bfloat16(v[e] - hif);
            const int base = (b_ * KW + (j_ >> 1)) * 4 + (j_ & 1);
            Wu[base]     = __bfloat16_as_ushort(hi);
            Wu[base + 2] = __bfloat16_as_ushort(lo);
            gbase[goff[e]] = v[e];
        }
        // x(t+1) into the other buffer
        C[(s + 1) & 1][xw] = make_uint2(bfpack(xn.x, xn.y),
                                        bfpack(bfres(xn.x), bfres(xn.y)));
        gbase += gstep;

        __syncthreads();   // step-s reads done; buffer (s+1)&1 fully written
    }
}

// ===== fc head: out[b][t] = fcb + <h_fw,fcW[0:128]> + <h_bw,fcW[128:256]>
__global__ __launch_bounds__(256)
void birnn_fc(const float* __restrict__ fcW, const float* __restrict__ fcb,
              float* __restrict__ out)
{
    const int gw   = (blockIdx.x * blockDim.x + threadIdx.x) >> 5;
    const int lane = threadIdx.x & 31;
    const int b = gw >> 10;
    const int t = gw & 1023;

    const float4* hf = (const float4*)(g_h + ((size_t)b * SLEN + t) * HID);
    const float4* hb = (const float4*)(g_h + ((size_t)(BATCH + b) * SLEN + t) * HID);
    float4 a  = hf[lane];
    float4 c  = hb[lane];
    float4 wa = ((const float4*)fcW)[lane];
    float4 wb = ((const float4*)fcW)[32 + lane];

    float s = a.x*wa.x + a.y*wa.y + a.z*wa.z + a.w*wa.w
            + c.x*wb.x + c.y*wb.y + c.z*wb.z + c.w*wb.w;
    #pragma unroll
    for (int m = 16; m > 0; m >>= 1)
        s += __shfl_xor_sync(0xffffffffu, s, m);
    if (lane == 0) out[gw] = s + fcb[0];
}

extern "C" void kernel_launch(void* const* d_in, const int* in_sizes, int n_in,
                              void* d_out, int out_size)
{
    (void)in_sizes; (void)n_in; (void)out_size;
    const float* inputs = (const float*)d_in[0];
    const float* Wih_fw = (const float*)d_in[1];
    const float* Whh_fw = (const float*)d_in[2];
    const float* bih_fw = (const float*)d_in[3];
    const float* bhh_fw = (const float*)d_in[4];
    const float* Wih_bw = (const float*)d_in[5];
    const float* Whh_bw = (const float*)d_in[6];
    const float* bih_bw = (const float*)d_in[7];
    const float* bhh_bw = (const float*)d_in[8];
    const float* fcW    = (const float*)d_in[9];
    const float* fcb    = (const float*)d_in[10];
    float* out = (float*)d_out;

    birnn_recur<<<64, 256>>>(inputs, Whh_fw, Whh_bw, Wih_fw, Wih_bw,
                             bih_fw, bhh_fw, bih_bw, bhh_bw);
    birnn_fc<<<(BATCH * SLEN) / 8, 256>>>(fcW, fcb, out);
}